// round 2
// baseline (speedup 1.0000x reference)
#include <cuda_runtime.h>

#define DIM   512
#define CDIM  12
#define NTOK  16384
#define CSIZE 4096
#define GRID  128
#define BLK   512

#define OUT_OFF_IDX (NTOK * DIM)            // 8388608
#define OUT_OFF_AUX (OUT_OFF_IDX + NTOK)    // 8404992
#define LOG_EPS_NEG 11.512925464970229f     // -ln(1e-5)
#define A_MAX       20.723265837f           // ln(1e9): exp(-a) > 1e-9 filter

// ---- device scratch (no allocations allowed) ----
__device__ float g_avg[CSIZE];   // sum over samples of per-code prob
__device__ float g_pse;          // sum over samples of per-sample entropy
__device__ int   g_flag = 0;     // "accumulators zeroed" release flag
__device__ int   g_cnt  = 0;     // finished-block counter

// ---------------------------------------------------------------------------
// Single fused kernel: zero-init (block 0) + in-proj + quantize + indices +
// factorized-softmax entropy + out-proj + last-block finalize.
// grid 128 x block 512, 48 KB dynamic smem (w_in + w_out^T), 8 tokens/warp.
// ---------------------------------------------------------------------------
__global__ void __launch_bounds__(BLK, 1)
mainK(const float* __restrict__ x,
      const float* __restrict__ w_in,
      const float* __restrict__ b_in,
      const float* __restrict__ w_out,
      const float* __restrict__ b_out,
      float* __restrict__ out)
{
    extern __shared__ float sm[];
    float* s_win  = sm;               // [c][d]
    float* s_wout = sm + CDIM * DIM;  // transposed: [c][d]

    // block 0 zeros the cross-block accumulators
    if (blockIdx.x == 0) {
        for (int i = threadIdx.x; i < CSIZE; i += BLK) g_avg[i] = 0.f;
        if (threadIdx.x == 0) g_pse = 0.f;
    }

    // stage weights
    for (int i = threadIdx.x; i < CDIM * DIM; i += BLK) {
        s_win[i] = w_in[i];
        int d = i / CDIM, c = i % CDIM;           // w_out is [512][12]
        s_wout[c * DIM + d] = w_out[i];
    }
    __syncthreads();

    // release flag (zero-stores are complete block-wide past the barrier)
    if (blockIdx.x == 0 && threadIdx.x == 0) {
        __threadfence();
        atomicExch(&g_flag, 1);
    }

    const int wid  = threadIdx.x >> 5;
    const int lane = threadIdx.x & 31;
    const int gw   = blockIdx.x * (BLK >> 5) + wid;   // 0..2047

    float bin[CDIM];
#pragma unroll
    for (int c = 0; c < CDIM; c++) bin[c] = b_in[c];

    const float4* X4  = (const float4*)x;
    float4*       O4  = (float4*)out;
    const float4* W4  = (const float4*)s_win;
    const float4* WO4 = (const float4*)s_wout;
    const float4* BO4 = (const float4*)b_out;

    float pse_acc = 0.f;     // nonzero on lane 0 only
    bool  flag_ok = false;

#pragma unroll
    for (int g = 0; g < 2; g++) {
        const int tok0 = gw * 8 + g * 4;

        // ---- in-projection ----
        float acc[4][CDIM];
#pragma unroll
        for (int t = 0; t < 4; t++)
#pragma unroll
            for (int c = 0; c < CDIM; c++) acc[t][c] = 0.f;

#pragma unroll
        for (int i = 0; i < 4; i++) {
            const int off = i * 32 + lane;
            float4 w[CDIM];
#pragma unroll
            for (int c = 0; c < CDIM; c++) w[c] = W4[c * 128 + off];
#pragma unroll
            for (int t = 0; t < 4; t++) {
                float4 xv = X4[(size_t)(tok0 + t) * 128 + off];
#pragma unroll
                for (int c = 0; c < CDIM; c++) {
                    acc[t][c] += xv.x * w[c].x + xv.y * w[c].y
                               + xv.z * w[c].z + xv.w * w[c].w;
                }
            }
        }

        // warp butterfly -> every lane holds full xp for all 4 tokens
#pragma unroll
        for (int t = 0; t < 4; t++)
#pragma unroll
            for (int c = 0; c < CDIM; c++) {
                float v = acc[t][c];
                v += __shfl_xor_sync(0xffffffffu, v, 16);
                v += __shfl_xor_sync(0xffffffffu, v, 8);
                v += __shfl_xor_sync(0xffffffffu, v, 4);
                v += __shfl_xor_sync(0xffffffffu, v, 2);
                v += __shfl_xor_sync(0xffffffffu, v, 1);
                acc[t][c] = v + bin[c];
            }

        // ---- indices ----
        int idx[4];
#pragma unroll
        for (int t = 0; t < 4; t++) {
            int ix = 0;
#pragma unroll
            for (int c = 0; c < CDIM; c++)
                if (acc[t][c] > 0.f) ix |= 1 << (11 - c);
            idx[t] = ix;
        }

        // ---- lane 0: indices out + adaptive entropy (factorized softmax) ----
        if (lane == 0) {
            if (!flag_ok) {
                while (((volatile int*)&g_flag)[0] == 0) { }
                flag_ok = true;
            }
#pragma unroll
            for (int t = 0; t < 4; t++) {
                out[OUT_OFF_IDX + tok0 + t] = (float)idx[t];

                float ta[CDIM], aa[CDIM];
                int   ma[CDIM];
                int   k = 0;
                float Z = 1.f;
#pragma unroll
                for (int c = 0; c < CDIM; c++) {
                    float a = 400.f * fabsf(acc[t][c]);
                    if (a < A_MAX) {
                        float e = expf(-a);
                        ta[k] = e; aa[k] = a; ma[k] = 1 << (11 - c);
                        k++;
                        Z *= (1.f + e);
                    }
                }
                float logZ = logf(Z);
                float invZ = 1.f / Z;
                int n = 1 << k;
                for (int s = 0; s < n; s++) {
                    float p = invZ, A = logZ;
                    int ix = idx[t];
                    for (int j = 0; j < k; j++) {
                        if ((s >> j) & 1) { p *= ta[j]; A += aa[j]; ix ^= ma[j]; }
                    }
                    pse_acc += p * fminf(A, LOG_EPS_NEG);
                    atomicAdd(&g_avg[ix], p);
                }
            }
        }

        // ---- quantize (x_st == quantized on forward path) + out-proj ----
        float q[4][CDIM];
#pragma unroll
        for (int t = 0; t < 4; t++)
#pragma unroll
            for (int c = 0; c < CDIM; c++)
                q[t][c] = acc[t][c] > 0.f ? 1.f : -1.f;

#pragma unroll
        for (int i = 0; i < 4; i++) {
            const int off = i * 32 + lane;
            float4 w[CDIM];
#pragma unroll
            for (int c = 0; c < CDIM; c++) w[c] = WO4[c * 128 + off];
            float4 bo = BO4[off];
#pragma unroll
            for (int t = 0; t < 4; t++) {
                float4 o = bo;
#pragma unroll
                for (int c = 0; c < CDIM; c++) {
                    o.x += q[t][c] * w[c].x;
                    o.y += q[t][c] * w[c].y;
                    o.z += q[t][c] * w[c].z;
                    o.w += q[t][c] * w[c].w;
                }
                O4[(size_t)(tok0 + t) * 128 + off] = o;
            }
        }
    }

    // ---- block-reduce pse (weights dead past this barrier; reuse smem) ----
    __syncthreads();
    if (lane == 0) sm[wid] = pse_acc;
    __syncthreads();
    if (wid == 0) {
        float v = (lane < (BLK >> 5)) ? sm[lane] : 0.f;
        v += __shfl_xor_sync(0xffffffffu, v, 8);
        v += __shfl_xor_sync(0xffffffffu, v, 4);
        v += __shfl_xor_sync(0xffffffffu, v, 2);
        v += __shfl_xor_sync(0xffffffffu, v, 1);
        if (lane == 0) atomicAdd(&g_pse, v);
    }

    // ---- last-block finalize ----
    __threadfence();
    __syncthreads();
    int* s_last = (int*)&sm[16];
    if (threadIdx.x == 0) {
        int old = atomicAdd(&g_cnt, 1);
        *s_last = (old == (int)gridDim.x - 1) ? 1 : 0;
    }
    __syncthreads();
    if (*s_last) {
        __threadfence();
        const float inv = 1.f / (float)NTOK;
        float ce = 0.f;
        for (int i = threadIdx.x; i < CSIZE; i += BLK) {
            float ap = __ldcg(&g_avg[i]) * inv;
            ce += -ap * logf(fmaxf(ap, 1e-5f));
        }
        float* red = sm + 64;
        red[threadIdx.x] = ce;
        __syncthreads();
        for (int s = BLK / 2; s > 0; s >>= 1) {
            if (threadIdx.x < (unsigned)s) red[threadIdx.x] += red[threadIdx.x + s];
            __syncthreads();
        }
        if (threadIdx.x == 0) {
            float aux = (__ldcg(&g_pse) * inv - red[0]) * 0.1f;
            out[OUT_OFF_AUX] = aux;
            g_cnt  = 0;   // reset for next graph replay
            g_flag = 0;
        }
    }
}

// ---------------------------------------------------------------------------
extern "C" void kernel_launch(void* const* d_in, const int* in_sizes, int n_in,
                              void* d_out, int out_size)
{
    const float* x     = (const float*)d_in[0];
    const float* w_in  = (const float*)d_in[1];
    const float* b_in  = (const float*)d_in[2];
    const float* w_out = (const float*)d_in[3];
    const float* b_out = (const float*)d_in[4];
    float* out = (float*)d_out;

    const size_t smem = (size_t)(2 * CDIM * DIM) * sizeof(float);  // 49152 B
    mainK<<<GRID, BLK, smem>>>(x, w_in, b_in, w_out, b_out, out);
}

// round 5
// speedup vs baseline: 2.5899x; 2.5899x over previous
#include <cuda_runtime.h>

#define DIM   512
#define CDIM  12
#define NTOK  16384
#define CSIZE 4096
#define GRID  512
#define BLK   256
#define NPASS 2

#define OUT_OFF_IDX (NTOK * DIM)            // 8388608
#define OUT_OFF_AUX (OUT_OFF_IDX + NTOK)    // 8404992
#define LOG_EPS_NEG 11.512925464970229f     // -ln(1e-5)
#define A_MAX       20.723265837f           // ln(1e9): exp(-a) > 1e-9 filter

// ---- device scratch (no allocations allowed) ----
__device__ float g_avg[CSIZE];   // sum over samples of per-code prob
__device__ float g_pse;          // sum over samples of per-sample entropy
__device__ int   g_flag = 0;     // "accumulators zeroed" release flag
__device__ int   g_cnt  = 0;     // finished-block counter

// ---------------------------------------------------------------------------
// Single fused kernel. grid 512 x block 256, 4 CTAs/SM (one wave), 48KB smem.
// Each warp: 4 tokens (2 passes x 2). Entropy is warp-cooperative: lane s
// evaluates code-subset s. pse_acc lives on ALL lanes -> warp-reduced at end.
// ---------------------------------------------------------------------------
__global__ void __launch_bounds__(BLK, 4)
mainK(const float* __restrict__ x,
      const float* __restrict__ w_in,
      const float* __restrict__ b_in,
      const float* __restrict__ w_out,
      const float* __restrict__ b_out,
      float* __restrict__ out)
{
    extern __shared__ float sm[];
    float* s_win  = sm;               // [c][d]
    float* s_wout = sm + CDIM * DIM;  // w_out transposed: [c][d]

    // block 0 zeros the cross-block accumulators, then releases g_flag
    if (blockIdx.x == 0) {
        for (int i = threadIdx.x; i < CSIZE; i += BLK) g_avg[i] = 0.f;
        if (threadIdx.x == 0) g_pse = 0.f;
    }

    // stage weights
    for (int i = threadIdx.x; i < CDIM * DIM; i += BLK) {
        s_win[i] = w_in[i];
        int d = i / CDIM, c = i % CDIM;           // w_out is [512][12]
        s_wout[c * DIM + d] = w_out[i];
    }
    __syncthreads();

    if (blockIdx.x == 0 && threadIdx.x == 0) {
        __threadfence();
        atomicExch(&g_flag, 1);
    }

    const int wid  = threadIdx.x >> 5;
    const int lane = threadIdx.x & 31;
    const int gw   = blockIdx.x * (BLK >> 5) + wid;   // 0..4095

    const float4* X4  = (const float4*)x;
    float4*       O4  = (float4*)out;
    const float4* W4  = (const float4*)s_win;
    const float4* WO4 = (const float4*)s_wout;
    const float4* BO4 = (const float4*)b_out;

    float pse_acc = 0.f;      // distributed across all lanes
    bool  flagged = false;

#pragma unroll
    for (int p = 0; p < NPASS; p++) {
        const int tok0 = gw * 4 + p * 2;

        // ---- in-projection (2 tokens) ----
        float acc[2][CDIM];
#pragma unroll
        for (int c = 0; c < CDIM; c++) { acc[0][c] = 0.f; acc[1][c] = 0.f; }

#pragma unroll
        for (int i = 0; i < 4; i++) {
            const int off = i * 32 + lane;
            float4 x0 = X4[(size_t)tok0 * 128 + off];
            float4 x1 = X4[(size_t)(tok0 + 1) * 128 + off];
#pragma unroll
            for (int c = 0; c < CDIM; c++) {
                float4 w = W4[c * 128 + off];
                acc[0][c] += x0.x * w.x + x0.y * w.y + x0.z * w.z + x0.w * w.w;
                acc[1][c] += x1.x * w.x + x1.y * w.y + x1.z * w.z + x1.w * w.w;
            }
        }

        // butterfly -> every lane holds full xp for both tokens
#pragma unroll
        for (int t = 0; t < 2; t++)
#pragma unroll
            for (int c = 0; c < CDIM; c++) {
                float v = acc[t][c];
                v += __shfl_xor_sync(0xffffffffu, v, 16);
                v += __shfl_xor_sync(0xffffffffu, v, 8);
                v += __shfl_xor_sync(0xffffffffu, v, 4);
                v += __shfl_xor_sync(0xffffffffu, v, 2);
                v += __shfl_xor_sync(0xffffffffu, v, 1);
                acc[t][c] = v + b_in[c];
            }

        // ---- indices ----
        int idx[2];
#pragma unroll
        for (int t = 0; t < 2; t++) {
            int ix = 0;
#pragma unroll
            for (int c = 0; c < CDIM; c++)
                if (acc[t][c] > 0.f) ix |= 1 << (11 - c);
            idx[t] = ix;
        }

        // wait for accumulator zero-init (nearly always already set)
        if (!flagged) {
            while (*(volatile int*)&g_flag == 0) { }
            flagged = true;
        }

        // ---- entropy: factorized softmax, warp-cooperative ----
#pragma unroll
        for (int t = 0; t < 2; t++) {
            if (lane == 0) out[OUT_OFF_IDX + tok0 + t] = (float)idx[t];

            unsigned m = 0;                     // active-dim mask (uniform)
#pragma unroll
            for (int c = 0; c < CDIM; c++)
                if (400.f * fabsf(acc[t][c]) < A_MAX) m |= 1u << c;

            if (m == 0) {                       // ~32% of tokens: p(code)=1
                if (lane == 0) atomicAdd(&g_avg[idx[t]], 1.f);
            } else {
                const int k = __popc(m);
                float Z = 1.f;
#pragma unroll
                for (int c = 0; c < CDIM; c++)
                    if ((m >> c) & 1)
                        Z *= 1.f + expf(-400.f * fabsf(acc[t][c]));
                const float logZ = logf(Z);
                const float invZ = 1.f / Z;
                const int   n    = 1 << k;

                for (int base = 0; base < n; base += 32) {
                    const int sub = base + lane;
                    if (sub < n) {
                        float pp = invZ, A = logZ;
                        int   ix = idx[t];
                        int   j  = 0;
#pragma unroll
                        for (int c = 0; c < CDIM; c++) {
                            if ((m >> c) & 1) {
                                if ((sub >> j) & 1) {
                                    float a = 400.f * fabsf(acc[t][c]);
                                    pp *= expf(-a);
                                    A  += a;
                                    ix ^= 1 << (11 - c);
                                }
                                j++;
                            }
                        }
                        pse_acc += pp * fminf(A, LOG_EPS_NEG);
                        atomicAdd(&g_avg[ix], pp);
                    }
                }
            }
        }

        // ---- out-projection (x_st == quantized on fwd path; sign from idx)
#pragma unroll
        for (int i = 0; i < 4; i++) {
            const int off = i * 32 + lane;
            float4 bo = BO4[off];
            float4 o0 = bo, o1 = bo;
#pragma unroll
            for (int c = 0; c < CDIM; c++) {
                float4 w = WO4[c * 128 + off];
                float s0 = ((idx[0] >> (11 - c)) & 1) ? 1.f : -1.f;
                float s1 = ((idx[1] >> (11 - c)) & 1) ? 1.f : -1.f;
                o0.x += s0 * w.x; o0.y += s0 * w.y;
                o0.z += s0 * w.z; o0.w += s0 * w.w;
                o1.x += s1 * w.x; o1.y += s1 * w.y;
                o1.z += s1 * w.z; o1.w += s1 * w.w;
            }
            O4[(size_t)tok0 * 128 + off]       = o0;
            O4[(size_t)(tok0 + 1) * 128 + off] = o1;
        }
    }

    // ---- warp-reduce pse (ALL lanes hold contributions), then block-reduce
    pse_acc += __shfl_xor_sync(0xffffffffu, pse_acc, 16);
    pse_acc += __shfl_xor_sync(0xffffffffu, pse_acc, 8);
    pse_acc += __shfl_xor_sync(0xffffffffu, pse_acc, 4);
    pse_acc += __shfl_xor_sync(0xffffffffu, pse_acc, 2);
    pse_acc += __shfl_xor_sync(0xffffffffu, pse_acc, 1);

    __syncthreads();                   // weights dead; reuse smem
    if (lane == 0) sm[wid] = pse_acc;
    __syncthreads();
    if (wid == 0) {
        float v = (lane < (BLK >> 5)) ? sm[lane] : 0.f;
        v += __shfl_xor_sync(0xffffffffu, v, 4);
        v += __shfl_xor_sync(0xffffffffu, v, 2);
        v += __shfl_xor_sync(0xffffffffu, v, 1);
        if (lane == 0) atomicAdd(&g_pse, v);
    }

    // ---- last-block finalize ----
    __threadfence();
    __syncthreads();
    int* s_last = (int*)&sm[16];
    if (threadIdx.x == 0) {
        int old = atomicAdd(&g_cnt, 1);
        *s_last = (old == (int)gridDim.x - 1) ? 1 : 0;
    }
    __syncthreads();
    if (*s_last) {
        __threadfence();
        const float inv = 1.f / (float)NTOK;
        float ce = 0.f;
        for (int i = threadIdx.x; i < CSIZE; i += BLK) {
            float ap = __ldcg(&g_avg[i]) * inv;
            ce += -ap * logf(fmaxf(ap, 1e-5f));
        }
        float* red = sm + 64;
        red[threadIdx.x] = ce;
        __syncthreads();
        for (int s = BLK / 2; s > 0; s >>= 1) {
            if (threadIdx.x < (unsigned)s) red[threadIdx.x] += red[threadIdx.x + s];
            __syncthreads();
        }
        if (threadIdx.x == 0) {
            float aux = (__ldcg(&g_pse) * inv - red[0]) * 0.1f;
            out[OUT_OFF_AUX] = aux;
            g_cnt  = 0;   // reset for next graph replay
            g_flag = 0;
        }
    }
}

// ---------------------------------------------------------------------------
extern "C" void kernel_launch(void* const* d_in, const int* in_sizes, int n_in,
                              void* d_out, int out_size)
{
    const float* x     = (const float*)d_in[0];
    const float* w_in  = (const float*)d_in[1];
    const float* b_in  = (const float*)d_in[2];
    const float* w_out = (const float*)d_in[3];
    const float* b_out = (const float*)d_in[4];
    float* out = (float*)d_out;

    const size_t smem = (size_t)(2 * CDIM * DIM) * sizeof(float);  // 49152 B
    mainK<<<GRID, BLK, smem>>>(x, w_in, b_in, w_out, b_out, out);
}

// round 6
// speedup vs baseline: 3.1709x; 1.2243x over previous
#include <cuda_runtime.h>

#define DIM   512
#define CDIM  12
#define NTOK  16384
#define CSIZE 4096
#define GRID  512
#define BLK   256
#define NPASS 2

#define OUT_OFF_IDX (NTOK * DIM)            // 8388608
#define OUT_OFF_AUX (OUT_OFF_IDX + NTOK)    // 8404992
#define LOG_EPS_NEG 11.512925464970229f     // -ln(1e-5)
#define A_MAX       20.723265837f           // ln(1e9)
#define FULL        0xffffffffu

// ---- device scratch (no allocations allowed) ----
__device__ float g_avg[CSIZE];
__device__ float g_pse;
__device__ int   g_flag = 0;
__device__ int   g_cnt  = 0;

typedef unsigned long long u64;

__device__ __forceinline__ u64 fma2(u64 a, u64 b, u64 c) {
    u64 d; asm("fma.rn.f32x2 %0, %1, %2, %3;" : "=l"(d) : "l"(a), "l"(b), "l"(c));
    return d;
}
__device__ __forceinline__ u64 add2(u64 a, u64 b) {
    u64 d; asm("add.rn.f32x2 %0, %1, %2;" : "=l"(d) : "l"(a), "l"(b));
    return d;
}
__device__ __forceinline__ u64 pack2(float lo, float hi) {
    u64 d; asm("mov.b64 %0, {%1, %2};" : "=l"(d) : "f"(lo), "f"(hi));
    return d;
}
__device__ __forceinline__ float fold2(u64 v) {   // lo + hi
    float lo, hi; asm("mov.b64 {%0, %1}, %2;" : "=f"(lo), "=f"(hi) : "l"(v));
    return lo + hi;
}

// ---------------------------------------------------------------------------
// Single fused kernel. grid 512 x block 256 (4 CTAs/SM, one wave), 28KB smem.
// 4 tokens/warp. In-proj: FFMA2 packed, reduce-scatter (xp_c lands on lane 2c),
// sign/activity via ballot. Entropy: factorized softmax, warp-parallel subsets.
// Out-proj: sparse +-2*w subset sum against precomputed (b_out -+ S).
// ---------------------------------------------------------------------------
__global__ void __launch_bounds__(BLK, 4)
mainK(const float* __restrict__ x,
      const float* __restrict__ w_in,
      const float* __restrict__ b_in,
      const float* __restrict__ w_out,
      const float* __restrict__ b_out,
      float* __restrict__ out)
{
    __shared__ float s_wt[CDIM * DIM];   // w_out transposed [c][d]
    __shared__ float s_bm[DIM];          // b_out - S
    __shared__ float s_bp[DIM];          // b_out + S
    __shared__ int   s_last;

    if (blockIdx.x == 0) {
        for (int i = threadIdx.x; i < CSIZE; i += BLK) g_avg[i] = 0.f;
        if (threadIdx.x == 0) g_pse = 0.f;
    }

    // stage: transpose w_out, build b_out -+ S  (S = sum_c w_out[d][c])
    for (int d = threadIdx.x; d < DIM; d += BLK) {
        float S = 0.f;
#pragma unroll
        for (int c = 0; c < CDIM; c++) {
            float w = w_out[d * CDIM + c];
            s_wt[c * DIM + d] = w;
            S += w;
        }
        float b = b_out[d];
        s_bm[d] = b - S;
        s_bp[d] = b + S;
    }
    __syncthreads();

    if (blockIdx.x == 0 && threadIdx.x == 0) {
        __threadfence();
        atomicExch(&g_flag, 1);
    }

    const int wid   = threadIdx.x >> 5;
    const int lane  = threadIdx.x & 31;
    const int gw    = blockIdx.x * (BLK >> 5) + wid;   // 0..4095
    const int c_own = (lane >> 1) & 15;                // c owned by this lane
    const float b_lane = (c_own < CDIM) ? __ldg(&b_in[c_own]) : 0.f;

    const ulonglong2* X2  = (const ulonglong2*)x;
    const ulonglong2* W2  = (const ulonglong2*)w_in;
    const ulonglong2* WT2 = (const ulonglong2*)s_wt;
    ulonglong2*       O2  = (ulonglong2*)out;

    float pse_acc = 0.f;
    bool  flagged = false;

#pragma unroll
    for (int p = 0; p < NPASS; p++) {
        const int tok0 = gw * 4 + p * 2;

        // ---- in-projection: packed FFMA2, chunked over c (6 at a time) ----
        float vv[2][CDIM];
#pragma unroll
        for (int ch = 0; ch < 2; ch++) {
            u64 a2[2][6];
#pragma unroll
            for (int cc = 0; cc < 6; cc++) { a2[0][cc] = 0ull; a2[1][cc] = 0ull; }
#pragma unroll
            for (int i = 0; i < 4; i++) {
                const int off = i * 32 + lane;
                ulonglong2 x0 = X2[(size_t)tok0 * 128 + off];
                ulonglong2 x1 = X2[(size_t)(tok0 + 1) * 128 + off];
#pragma unroll
                for (int cc = 0; cc < 6; cc++) {
                    ulonglong2 w = W2[(ch * 6 + cc) * 128 + off];
                    a2[0][cc] = fma2(x0.x, w.x, a2[0][cc]);
                    a2[0][cc] = fma2(x0.y, w.y, a2[0][cc]);
                    a2[1][cc] = fma2(x1.x, w.x, a2[1][cc]);
                    a2[1][cc] = fma2(x1.y, w.y, a2[1][cc]);
                }
            }
#pragma unroll
            for (int cc = 0; cc < 6; cc++) {
                vv[0][ch * 6 + cc] = fold2(a2[0][cc]);
                vv[1][ch * 6 + cc] = fold2(a2[1][cc]);
            }
        }

        if (!flagged) {
            while (*(volatile int*)&g_flag == 0) { }
            flagged = true;
        }

        // ---- per-token: reduce-scatter -> ballots -> entropy -> out-proj ----
#pragma unroll
        for (int t = 0; t < 2; t++) {
            // reduce-scatter: sum over lanes; c lands on lanes 2c, 2c+1.
            float r8[8];
#pragma unroll
            for (int j = 0; j < 8; j++) {
                float hiV  = (j + 8 < CDIM) ? vv[t][j + 8] : 0.f;
                float send = (lane & 16) ? vv[t][j] : hiV;
                float keep = (lane & 16) ? hiV : vv[t][j];
                r8[j] = keep + __shfl_xor_sync(FULL, send, 16);
            }
            float r4[4];
#pragma unroll
            for (int j = 0; j < 4; j++) {
                float send = (lane & 8) ? r8[j] : r8[j + 4];
                float keep = (lane & 8) ? r8[j + 4] : r8[j];
                r4[j] = keep + __shfl_xor_sync(FULL, send, 8);
            }
            float r2[2];
#pragma unroll
            for (int j = 0; j < 2; j++) {
                float send = (lane & 4) ? r4[j] : r4[j + 2];
                float keep = (lane & 4) ? r4[j + 2] : r4[j];
                r2[j] = keep + __shfl_xor_sync(FULL, send, 4);
            }
            float send = (lane & 2) ? r2[0] : r2[1];
            float keep = (lane & 2) ? r2[1] : r2[0];
            float r1 = keep + __shfl_xor_sync(FULL, send, 2);
            r1 += __shfl_xor_sync(FULL, r1, 1);

            const float xp = r1 + b_lane;               // xp for c_own
            const float a  = 400.f * fabsf(xp);

            unsigned sb  = __ballot_sync(FULL, xp > 0.f);
            unsigned act = __ballot_sync(FULL, a < A_MAX) & 0x00555555u;

            // index: compress even bits of sb (bit 2c -> bit c), then reverse
            unsigned e = sb & 0x00555555u;
            e = (e | (e >> 1)) & 0x33333333u;
            e = (e | (e >> 2)) & 0x0F0F0F0Fu;
            e = (e | (e >> 4)) & 0x00FF00FFu;
            e = (e | (e >> 8)) & 0x0000FFFFu;
            const int idx = (int)(__brev(e) >> 20);

            if (lane == 0) out[OUT_OFF_IDX + tok0 + t] = (float)idx;

            // ---- entropy ----
            if (act == 0u) {
                if (lane == 0) atomicAdd(&g_avg[idx], 1.f);
            } else {
                const int k = __popc(act);
                float Z = 1.f;
                unsigned mm = act;
                while (mm) {
                    int b = __ffs(mm) - 1;
                    float ac = __shfl_sync(FULL, a, b);
                    Z *= 1.f + expf(-ac);
                    mm &= mm - 1;
                }
                const float logZ = logf(Z);
                const float invZ = 1.f / Z;
                const int   n    = 1 << k;
                for (int base = 0; base < n; base += 32) {
                    const int sub = base + lane;
                    float Asum = 0.f;
                    int   ix   = idx, j = 0;
                    mm = act;
                    while (mm) {
                        int b = __ffs(mm) - 1;
                        int c = b >> 1;
                        float ac = __shfl_sync(FULL, a, b);
                        if ((sub >> j) & 1) { Asum += ac; ix ^= 1 << (11 - c); }
                        mm &= mm - 1; j++;
                    }
                    if (sub < n) {
                        float pp = invZ * expf(-Asum);
                        pse_acc += pp * fminf(Asum + logZ, LOG_EPS_NEG);
                        atomicAdd(&g_avg[ix], pp);
                    }
                }
            }

            // ---- sparse out-projection ----
            const int pc = __popc((unsigned)idx);
            unsigned bits = (pc <= 6) ? (unsigned)idx : (~(unsigned)idx & 0xFFFu);
            const float* bb = (pc <= 6) ? s_bm : s_bp;
            const u64 coef  = pack2(pc <= 6 ? 2.f : -2.f, pc <= 6 ? 2.f : -2.f);

            u64 o[8];
#pragma unroll
            for (int i = 0; i < 8; i++) o[i] = 0ull;
            while (bits) {
                int b = __ffs(bits) - 1;
                int c = 11 - b;
                const ulonglong2* W = WT2 + c * 128;
#pragma unroll
                for (int i = 0; i < 4; i++) {
                    ulonglong2 w = W[i * 32 + lane];
                    o[2 * i]     = add2(o[2 * i],     w.x);
                    o[2 * i + 1] = add2(o[2 * i + 1], w.y);
                }
                bits &= bits - 1;
            }
            const ulonglong2* B2 = (const ulonglong2*)bb;
#pragma unroll
            for (int i = 0; i < 4; i++) {
                ulonglong2 bv = B2[i * 32 + lane];
                ulonglong2 res;
                res.x = fma2(coef, o[2 * i],     bv.x);
                res.y = fma2(coef, o[2 * i + 1], bv.y);
                O2[(size_t)(tok0 + t) * 128 + i * 32 + lane] = res;
            }
        }
    }

    // ---- reduce pse: warp, then block, then global ----
    pse_acc += __shfl_xor_sync(FULL, pse_acc, 16);
    pse_acc += __shfl_xor_sync(FULL, pse_acc, 8);
    pse_acc += __shfl_xor_sync(FULL, pse_acc, 4);
    pse_acc += __shfl_xor_sync(FULL, pse_acc, 2);
    pse_acc += __shfl_xor_sync(FULL, pse_acc, 1);

    __syncthreads();                 // weights dead past here; reuse s_bm
    if (lane == 0) s_bm[wid] = pse_acc;
    __syncthreads();
    if (wid == 0) {
        float v = (lane < (BLK >> 5)) ? s_bm[lane] : 0.f;
        v += __shfl_xor_sync(FULL, v, 4);
        v += __shfl_xor_sync(FULL, v, 2);
        v += __shfl_xor_sync(FULL, v, 1);
        if (lane == 0) atomicAdd(&g_pse, v);
    }

    // ---- last-block finalize ----
    __threadfence();
    __syncthreads();
    if (threadIdx.x == 0) {
        int old = atomicAdd(&g_cnt, 1);
        s_last = (old == (int)gridDim.x - 1) ? 1 : 0;
    }
    __syncthreads();
    if (s_last) {
        __threadfence();
        const float inv = 1.f / (float)NTOK;
        float ce = 0.f;
        for (int i = threadIdx.x; i < CSIZE; i += BLK) {
            float ap = __ldcg(&g_avg[i]) * inv;
            ce += -ap * logf(fmaxf(ap, 1e-5f));
        }
        float* red = s_wt;           // reuse smem
        red[threadIdx.x] = ce;
        __syncthreads();
        for (int s = BLK / 2; s > 0; s >>= 1) {
            if (threadIdx.x < (unsigned)s) red[threadIdx.x] += red[threadIdx.x + s];
            __syncthreads();
        }
        if (threadIdx.x == 0) {
            float aux = (__ldcg(&g_pse) * inv - red[0]) * 0.1f;
            out[OUT_OFF_AUX] = aux;
            g_cnt  = 0;
            g_flag = 0;
        }
    }
}

// ---------------------------------------------------------------------------
extern "C" void kernel_launch(void* const* d_in, const int* in_sizes, int n_in,
                              void* d_out, int out_size)
{
    const float* x     = (const float*)d_in[0];
    const float* w_in  = (const float*)d_in[1];
    const float* b_in  = (const float*)d_in[2];
    const float* w_out = (const float*)d_in[3];
    const float* b_out = (const float*)d_in[4];
    float* out = (float*)d_out;

    mainK<<<GRID, BLK>>>(x, w_in, b_in, w_out, b_out, out);
}